// round 2
// baseline (speedup 1.0000x reference)
#include <cuda_runtime.h>
#include <math.h>

// Problem constants: B=16, C=32, O=32, K=3, H=W=128, T=34, EPS=1e-5
#define EPSF 1e-5f

// ---------------- scratch (no allocations allowed) ----------------
__device__ float g_pooled[16 * 64];              // [B][2C]
__device__ float g_theta[2 * 16 * 96];           // [branch][B][K*C]
__device__ float g_wmix[2 * 16 * 32 * 9 * 32];   // [branch][B][c][tap][o]  (1.18 MB)
__device__ float g_bmix[2 * 16 * 32];            // [branch][B][o]

// ================= pool: mean over HxW of concat(center,boundary) =================
__global__ void pool_kernel(const float* __restrict__ center,
                            const float* __restrict__ boundary) {
    int bid = blockIdx.x;            // 16*64 blocks
    int b = bid >> 6, ch = bid & 63;
    const float* src = (ch < 32)
        ? center   + (size_t)(b * 32 + ch)      * 16384
        : boundary + (size_t)(b * 32 + ch - 32) * 16384;
    const float4* s4 = (const float4*)src;
    float s = 0.f;
    for (int i = threadIdx.x; i < 4096; i += 256) {
        float4 v = s4[i];
        s += (v.x + v.y) + (v.z + v.w);
    }
    #pragma unroll
    for (int off = 16; off; off >>= 1) s += __shfl_down_sync(0xffffffffu, s, off);
    __shared__ float red[8];
    if ((threadIdx.x & 31) == 0) red[threadIdx.x >> 5] = s;
    __syncthreads();
    if (threadIdx.x == 0) {
        float t = 0.f;
        #pragma unroll
        for (int w = 0; w < 8; w++) t += red[w];
        g_pooled[b * 64 + ch] = t * (1.0f / 16384.0f);
    }
}

// ================= gate branch: fc->BN->relu->fc->BN->softmax/T =================
__global__ void gate_kernel(int ten,
    const float* __restrict__ w1,  const float* __restrict__ g1,
    const float* __restrict__ bb1, const float* __restrict__ rm1,
    const float* __restrict__ rv1,
    const float* __restrict__ w2,  const float* __restrict__ bias2,
    const float* __restrict__ g2,  const float* __restrict__ bb2,
    const float* __restrict__ rm2, const float* __restrict__ rv2) {
    int b = blockIdx.x;          // 16 blocks, 96 threads
    int t = threadIdx.x;
    __shared__ float xs[64], hs[64], zs[96], es[96], mred[2];
    if (t < 64) xs[t] = g_pooled[b * 64 + t];
    __syncthreads();
    if (t < 64) {
        float s = 0.f;
        #pragma unroll 8
        for (int i = 0; i < 64; i++) s += xs[i] * w1[t * 64 + i];
        s = (s - rm1[t]) * rsqrtf(rv1[t] + EPSF) * g1[t] + bb1[t];
        hs[t] = fmaxf(s, 0.f);
    }
    __syncthreads();
    {
        float s = bias2[t];
        #pragma unroll 8
        for (int i = 0; i < 64; i++) s += hs[i] * w2[t * 64 + i];
        s = (s - rm2[t]) * rsqrtf(rv2[t] + EPSF) * g2[t] + bb2[t];
        zs[t] = s * (1.0f / 34.0f);
    }
    __syncthreads();
    if (t == 0) {
        float m = -1e30f;
        for (int i = 0; i < 96; i++) m = fmaxf(m, zs[i]);
        mred[0] = m;
    }
    __syncthreads();
    es[t] = expf(zs[t] - mred[0]);
    __syncthreads();
    if (t == 0) {
        float s = 0.f;
        for (int i = 0; i < 96; i++) s += es[i];
        mred[1] = s;
    }
    __syncthreads();
    g_theta[(ten * 16 + b) * 96 + t] = es[t] / mred[1];
}

// ================= mix: w_mix[c][tap][o] = sum_k theta[k,c]*W[k,o,c,tap] =================
__global__ void mix_kernel(const float* __restrict__ aw,   // [3][32][32][9]
                           const float* __restrict__ ab) { // [3][32]
    int bid = blockIdx.x;          // 32 blocks, 256 threads
    int ten = bid >> 4, b = bid & 15;
    __shared__ float th[96], thm[3];
    int t = threadIdx.x;
    if (t < 96) th[t] = g_theta[(ten * 16 + b) * 96 + t];
    __syncthreads();
    if (t < 3) {
        float s = 0.f;
        for (int c = 0; c < 32; c++) s += th[t * 32 + c];
        thm[t] = s * (1.0f / 32.0f);
    }
    __syncthreads();
    float* wm = g_wmix + (size_t)(ten * 16 + b) * 9216;
    for (int e = t; e < 9216; e += 256) {
        int c  = e / 288;
        int rr = e - c * 288;
        int ij = rr >> 5;
        int o  = rr & 31;
        float s = 0.f;
        #pragma unroll
        for (int k = 0; k < 3; k++)
            s += th[k * 32 + c] * aw[((k * 32 + o) * 32 + c) * 9 + ij];
        wm[e] = s;
    }
    if (t < 32) {
        float s = 0.f;
        #pragma unroll
        for (int k = 0; k < 3; k++) s += thm[k] * ab[k * 32 + t];
        g_bmix[(ten * 16 + b) * 32 + t] = s;
    }
}

// ================= conv: per-sample 32->32ch 3x3, f32x2-packed FMA =================
#define RS 148   // skewed smem row stride (== 4 mod 32): stride-8 reads conflict-free

__device__ __forceinline__ int sidx(int row, int xw) {
    return row * RS + xw + (xw >> 5);
}
__device__ __forceinline__ unsigned long long pk2(float v) {
    unsigned long long r;
    asm("mov.b64 %0, {%1, %1};" : "=l"(r) : "f"(v));
    return r;
}
__device__ __forceinline__ void fma2(unsigned long long& d,
                                     unsigned long long a, unsigned long long b) {
    asm("fma.rn.f32x2 %0, %1, %2, %0;" : "+l"(d) : "l"(a), "l"(b));
}
__device__ __forceinline__ void unpk(unsigned long long v, float& lo, float& hi) {
    asm("mov.b64 {%0, %1}, %2;" : "=f"(lo), "=f"(hi) : "l"(v));
}

__global__ __launch_bounds__(256, 2)
void conv_kernel(const float* __restrict__ center,
                 const float* __restrict__ boundary,
                 float* __restrict__ out) {
    __shared__ float w_s[9216];          // [c][tap][o]  36 KB
    __shared__ float in_s[2][6 * RS];    // 2 x (6 rows, skewed) ~7 KB

    int bid = blockIdx.x;                // 2*16*32 = 1024 blocks
    int ten = bid >> 9;
    int b   = (bid >> 5) & 15;
    int y0  = (bid & 31) * 4;

    int tid = threadIdx.x;
    int og  = tid >> 6;        // 4 groups of 8 output channels
    int r   = (tid >> 4) & 3;  // row within 4-row tile
    int p   = tid & 15;        // x block (8 px each)

    const float* in = (ten == 0 ? center : boundary) + (size_t)b * 32 * 16384;

    // ---- load mixed weights into smem (float4, coalesced) ----
    {
        const float4* src = (const float4*)(g_wmix + (size_t)(ten * 16 + b) * 9216);
        float4* dst = (float4*)w_s;
        #pragma unroll
        for (int e = 0; e < 9; e++) dst[tid + e * 256] = src[tid + e * 256];
    }

    // ---- precompute staging addresses (identical across channels) ----
    // goff < 0  => halo/out-of-image (store 0);  sph < 0 => no slot for this it
    int goff[4], sph[4];
    #pragma unroll
    for (int it = 0; it < 4; it++) {
        int u = tid + it * 256;      // 6 rows x 131 xw entries = 786
        goff[it] = -1; sph[it] = -1;
        if (u < 786) {
            int row = u / 131, xw = u - row * 131;
            int y = y0 - 1 + row, x = xw - 1;
            sph[it] = sidx(row, xw);
            if ((unsigned)y < 128u && (unsigned)x < 128u) goff[it] = y * 128 + x;
        }
    }

    float stv[4];
    // stage channel 0
    #pragma unroll
    for (int it = 0; it < 4; it++)
        stv[it] = (goff[it] >= 0) ? __ldg(in + goff[it]) : 0.f;
    #pragma unroll
    for (int it = 0; it < 4; it++)
        if (sph[it] >= 0) in_s[0][sph[it]] = stv[it];
    __syncthreads();

    unsigned long long acc[4][8];
    #pragma unroll
    for (int op = 0; op < 4; op++)
        #pragma unroll
        for (int xx = 0; xx < 8; xx++) acc[op][xx] = 0ULL;

    for (int c = 0; c < 32; c++) {
        // prefetch next channel (LDG only; STS deferred to after compute)
        if (c + 1 < 32) {
            const float* nin = in + (size_t)(c + 1) * 16384;
            #pragma unroll
            for (int it = 0; it < 4; it++)
                stv[it] = (goff[it] >= 0) ? __ldg(nin + goff[it]) : 0.f;
        }

        const float* wc = w_s + c * 288;
        const float* ib = in_s[c & 1];
        #pragma unroll
        for (int i = 0; i < 3; i++) {
            unsigned long long xd[10];
            #pragma unroll
            for (int t2 = 0; t2 < 10; t2++)
                xd[t2] = pk2(ib[sidx(r + i, p * 8 + t2)]);
            #pragma unroll
            for (int j = 0; j < 3; j++) {
                unsigned long long w2r[4];
                #pragma unroll
                for (int op = 0; op < 4; op++)
                    w2r[op] = *(const unsigned long long*)(wc + i * 96 + j * 32 + og * 8 + 2 * op);
                #pragma unroll
                for (int xx = 0; xx < 8; xx++)
                    #pragma unroll
                    for (int op = 0; op < 4; op++)
                        fma2(acc[op][xx], w2r[op], xd[xx + j]);
            }
        }

        if (c + 1 < 32) {
            int nb = (c + 1) & 1;
            #pragma unroll
            for (int it = 0; it < 4; it++)
                if (sph[it] >= 0) in_s[nb][sph[it]] = stv[it];
        }
        __syncthreads();
    }

    // ---- epilogue: add mixed bias, store (two channels per op-pair) ----
    const float* bm = g_bmix + (ten * 16 + b) * 32;
    int y = y0 + r;
    #pragma unroll
    for (int op = 0; op < 4; op++) {
        int o0 = og * 8 + 2 * op;
        float bl = bm[o0], bh = bm[o0 + 1];
        float vl[8], vh[8];
        #pragma unroll
        for (int xx = 0; xx < 8; xx++) unpk(acc[op][xx], vl[xx], vh[xx]);
        size_t ob = ((size_t)(ten * 16 + b) * 32 + o0) * 16384 + (size_t)y * 128 + p * 8;
        float4 q;
        q.x = vl[0] + bl; q.y = vl[1] + bl; q.z = vl[2] + bl; q.w = vl[3] + bl;
        *(float4*)(out + ob) = q;
        q.x = vl[4] + bl; q.y = vl[5] + bl; q.z = vl[6] + bl; q.w = vl[7] + bl;
        *(float4*)(out + ob + 4) = q;
        q.x = vh[0] + bh; q.y = vh[1] + bh; q.z = vh[2] + bh; q.w = vh[3] + bh;
        *(float4*)(out + ob + 16384) = q;
        q.x = vh[4] + bh; q.y = vh[5] + bh; q.z = vh[6] + bh; q.w = vh[7] + bh;
        *(float4*)(out + ob + 16384 + 4) = q;
    }
}

// ================= launch =================
extern "C" void kernel_launch(void* const* d_in, const int* in_sizes, int n_in,
                              void* d_out, int out_size) {
    const float* center    = (const float*)d_in[0];
    const float* boundary  = (const float*)d_in[1];
    const float* aw        = (const float*)d_in[2];
    const float* ab        = (const float*)d_in[3];
    const float* fc1_1_w   = (const float*)d_in[4];
    const float* bn1_1_g   = (const float*)d_in[5];
    const float* bn1_1_b   = (const float*)d_in[6];
    const float* bn1_1_rm  = (const float*)d_in[7];
    const float* bn1_1_rv  = (const float*)d_in[8];
    const float* fc1_2_w   = (const float*)d_in[9];
    const float* fc1_2_b   = (const float*)d_in[10];
    const float* bn1_2_g   = (const float*)d_in[11];
    const float* bn1_2_b   = (const float*)d_in[12];
    const float* bn1_2_rm  = (const float*)d_in[13];
    const float* bn1_2_rv  = (const float*)d_in[14];
    const float* fc2_1_w   = (const float*)d_in[15];
    const float* bn2_1_g   = (const float*)d_in[16];
    const float* bn2_1_b   = (const float*)d_in[17];
    const float* bn2_1_rm  = (const float*)d_in[18];
    const float* bn2_1_rv  = (const float*)d_in[19];
    const float* fc2_2_w   = (const float*)d_in[20];
    const float* fc2_2_b   = (const float*)d_in[21];
    const float* bn2_2_g   = (const float*)d_in[22];
    const float* bn2_2_b   = (const float*)d_in[23];
    const float* bn2_2_rm  = (const float*)d_in[24];
    const float* bn2_2_rv  = (const float*)d_in[25];

    pool_kernel<<<1024, 256>>>(center, boundary);
    gate_kernel<<<16, 96>>>(0, fc1_1_w, bn1_1_g, bn1_1_b, bn1_1_rm, bn1_1_rv,
                            fc1_2_w, fc1_2_b, bn1_2_g, bn1_2_b, bn1_2_rm, bn1_2_rv);
    gate_kernel<<<16, 96>>>(1, fc2_1_w, bn2_1_g, bn2_1_b, bn2_1_rm, bn2_1_rv,
                            fc2_2_w, fc2_2_b, bn2_2_g, bn2_2_b, bn2_2_rm, bn2_2_rv);
    mix_kernel<<<32, 256>>>(aw, ab);
    conv_kernel<<<1024, 256>>>(center, boundary, (float*)d_out);
}

// round 3
// speedup vs baseline: 1.0999x; 1.0999x over previous
#include <cuda_runtime.h>
#include <math.h>

// Problem constants: B=16, C=32, O=32, K=3, H=W=128, T=34, EPS=1e-5
#define EPSF 1e-5f

// ---------------- scratch (no allocations allowed) ----------------
__device__ float g_pooled[16 * 64];              // [B][2C]
__device__ float g_wmix[2 * 16 * 32 * 9 * 32];   // [branch][B][c][tap][o]  (1.18 MB)
__device__ float g_bmix[2 * 16 * 32];            // [branch][B][o]

// ================= pool: mean over HxW of concat(center,boundary) =================
__global__ void pool_kernel(const float* __restrict__ center,
                            const float* __restrict__ boundary) {
    int bid = blockIdx.x;            // 16*64 blocks
    int b = bid >> 6, ch = bid & 63;
    const float* src = (ch < 32)
        ? center   + (size_t)(b * 32 + ch)      * 16384
        : boundary + (size_t)(b * 32 + ch - 32) * 16384;
    const float4* s4 = (const float4*)src;
    float s = 0.f;
    for (int i = threadIdx.x; i < 4096; i += 256) {
        float4 v = s4[i];
        s += (v.x + v.y) + (v.z + v.w);
    }
    #pragma unroll
    for (int off = 16; off; off >>= 1) s += __shfl_down_sync(0xffffffffu, s, off);
    __shared__ float red[8];
    if ((threadIdx.x & 31) == 0) red[threadIdx.x >> 5] = s;
    __syncthreads();
    if (threadIdx.x == 0) {
        float t = 0.f;
        #pragma unroll
        for (int w = 0; w < 8; w++) t += red[w];
        g_pooled[b * 64 + ch] = t * (1.0f / 16384.0f);
    }
}

// ======== gate+mix: fc->BN->relu->fc->BN->softmax, then weight mixing ========
// One block per (ten, b); 32 blocks x 256 threads.
// Mix reads aw coalesced (e = 288*o + 9*c + ij is linear), stages via a padded
// smem buffer (idx = e + e/288 = 289*o + 9*c + ij; 289 == 1 mod 32 -> both the
// linear write and the o-fastest gather are bank-conflict-free), accumulates
// the k-sum in registers, and writes g_wmix coalesced in conv layout.
__global__ __launch_bounds__(256, 1)
void gate_mix_kernel(
    const float* __restrict__ aw,   const float* __restrict__ ab,
    const float* __restrict__ w1a,  const float* __restrict__ g1a,
    const float* __restrict__ b1a,  const float* __restrict__ rm1a,
    const float* __restrict__ rv1a,
    const float* __restrict__ w2a,  const float* __restrict__ bias2a,
    const float* __restrict__ g2a,  const float* __restrict__ b2a,
    const float* __restrict__ rm2a, const float* __restrict__ rv2a,
    const float* __restrict__ w1b,  const float* __restrict__ g1b,
    const float* __restrict__ b1b,  const float* __restrict__ rm1b,
    const float* __restrict__ rv1b,
    const float* __restrict__ w2b,  const float* __restrict__ bias2b,
    const float* __restrict__ g2b,  const float* __restrict__ b2b,
    const float* __restrict__ rm2b, const float* __restrict__ rv2b) {

    int bid = blockIdx.x;
    int ten = bid >> 4, b = bid & 15;
    int t = threadIdx.x;

    const float* w1    = ten ? w1b    : w1a;
    const float* g1    = ten ? g1b    : g1a;
    const float* bb1   = ten ? b1b    : b1a;
    const float* rm1   = ten ? rm1b   : rm1a;
    const float* rv1   = ten ? rv1b   : rv1a;
    const float* w2    = ten ? w2b    : w2a;
    const float* bias2 = ten ? bias2b : bias2a;
    const float* g2    = ten ? g2b    : g2a;
    const float* bb2   = ten ? b2b    : b2a;
    const float* rm2   = ten ? rm2b   : rm2a;
    const float* rv2   = ten ? rv2b   : rv2a;

    __shared__ float xs[64], hs[64], th[96], mred[2], thm[3];
    __shared__ float buf[9248];   // 9216 + per-o-row pad of 1 (36992 B)

    // ---- gate branch ----
    if (t < 64) xs[t] = g_pooled[b * 64 + t];
    __syncthreads();
    if (t < 64) {
        float s = 0.f;
        #pragma unroll 8
        for (int i = 0; i < 64; i++) s += xs[i] * w1[t * 64 + i];
        s = (s - rm1[t]) * rsqrtf(rv1[t] + EPSF) * g1[t] + bb1[t];
        hs[t] = fmaxf(s, 0.f);
    }
    __syncthreads();
    if (t < 96) {
        float s = bias2[t];
        #pragma unroll 8
        for (int i = 0; i < 64; i++) s += hs[i] * w2[t * 64 + i];
        s = (s - rm2[t]) * rsqrtf(rv2[t] + EPSF) * g2[t] + bb2[t];
        th[t] = s * (1.0f / 34.0f);     // z/T
    }
    __syncthreads();
    if (t == 0) {
        float m = -1e30f;
        for (int i = 0; i < 96; i++) m = fmaxf(m, th[i]);
        mred[0] = m;
    }
    __syncthreads();
    if (t < 96) th[t] = expf(th[t] - mred[0]);
    __syncthreads();
    if (t == 0) {
        float s = 0.f;
        for (int i = 0; i < 96; i++) s += th[i];
        mred[1] = 1.0f / s;
    }
    __syncthreads();
    if (t < 96) th[t] *= mred[1];       // softmax done -> theta in th[]
    __syncthreads();

    // ---- bmix ----
    if (t < 3) {
        float s = 0.f;
        for (int c = 0; c < 32; c++) s += th[t * 32 + c];
        thm[t] = s * (1.0f / 32.0f);
    }
    __syncthreads();
    if (t < 32) {
        float s = 0.f;
        #pragma unroll
        for (int k = 0; k < 3; k++) s += thm[k] * ab[k * 32 + t];
        g_bmix[(ten * 16 + b) * 32 + t] = s;
    }

    // ---- wmix: wacc[d] = sum_k th[32k+c] * aw[k][o][c][ij], d = 288c+32ij+o ----
    float wacc[36];
    #pragma unroll
    for (int i = 0; i < 36; i++) wacc[i] = 0.f;

    // precompute per-thread gather metadata (d = t + 256*i)
    int gidx[36]; float thc[3][36];
    #pragma unroll
    for (int i = 0; i < 36; i++) {
        int d  = t + i * 256;
        int c  = d / 288;
        int rr = d - c * 288;
        int ij = rr >> 5;
        int o  = rr & 31;
        gidx[i] = 289 * o + 9 * c + ij;
        thc[0][i] = th[c]; thc[1][i] = th[32 + c]; thc[2][i] = th[64 + c];
    }

    #pragma unroll
    for (int k = 0; k < 3; k++) {
        // coalesced load of aw[k] -> padded smem (idx = e + e/288)
        const float* awk = aw + k * 9216;
        #pragma unroll
        for (int i = 0; i < 36; i++) {
            int e = t + i * 256;
            buf[e + e / 288] = __ldg(awk + e);
        }
        __syncthreads();
        #pragma unroll
        for (int i = 0; i < 36; i++)
            wacc[i] += thc[k][i] * buf[gidx[i]];
        __syncthreads();
    }

    float* wm = g_wmix + (size_t)(ten * 16 + b) * 9216;
    #pragma unroll
    for (int i = 0; i < 36; i++) wm[t + i * 256] = wacc[i];
}

// ================= conv: per-sample 32->32ch 3x3, f32x2-packed FMA =================
#define RS 148   // skewed smem row stride (== 4 mod 32): stride-8 reads conflict-free

__device__ __forceinline__ int sidx(int row, int xw) {
    return row * RS + xw + (xw >> 5);
}
__device__ __forceinline__ unsigned long long pk2(float v) {
    unsigned long long r;
    asm("mov.b64 %0, {%1, %1};" : "=l"(r) : "f"(v));
    return r;
}
__device__ __forceinline__ void fma2(unsigned long long& d,
                                     unsigned long long a, unsigned long long b) {
    asm("fma.rn.f32x2 %0, %1, %2, %0;" : "+l"(d) : "l"(a), "l"(b));
}
__device__ __forceinline__ void unpk(unsigned long long v, float& lo, float& hi) {
    asm("mov.b64 {%0, %1}, %2;" : "=f"(lo), "=f"(hi) : "l"(v));
}

__global__ __launch_bounds__(256, 2)
void conv_kernel(const float* __restrict__ center,
                 const float* __restrict__ boundary,
                 float* __restrict__ out) {
    __shared__ float w_s[9216];          // [c][tap][o]  36 KB
    __shared__ float in_s[2][6 * RS];    // 2 x (6 rows, skewed) ~7 KB

    int bid = blockIdx.x;                // 2*16*32 = 1024 blocks
    int ten = bid >> 9;
    int b   = (bid >> 5) & 15;
    int y0  = (bid & 31) * 4;

    int tid = threadIdx.x;
    int og  = tid >> 6;        // 4 groups of 8 output channels
    int r   = (tid >> 4) & 3;  // row within 4-row tile
    int p   = tid & 15;        // x block (8 px each)

    const float* in = (ten == 0 ? center : boundary) + (size_t)b * 32 * 16384;

    // ---- load mixed weights into smem (float4, coalesced) ----
    {
        const float4* src = (const float4*)(g_wmix + (size_t)(ten * 16 + b) * 9216);
        float4* dst = (float4*)w_s;
        #pragma unroll
        for (int e = 0; e < 9; e++) dst[tid + e * 256] = src[tid + e * 256];
    }

    // ---- precompute staging addresses (identical across channels) ----
    int goff[4], sph[4];
    #pragma unroll
    for (int it = 0; it < 4; it++) {
        int u = tid + it * 256;      // 6 rows x 131 xw entries = 786
        goff[it] = -1; sph[it] = -1;
        if (u < 786) {
            int row = u / 131, xw = u - row * 131;
            int y = y0 - 1 + row, x = xw - 1;
            sph[it] = sidx(row, xw);
            if ((unsigned)y < 128u && (unsigned)x < 128u) goff[it] = y * 128 + x;
        }
    }

    float stv[4];
    // stage channel 0
    #pragma unroll
    for (int it = 0; it < 4; it++)
        stv[it] = (goff[it] >= 0) ? __ldg(in + goff[it]) : 0.f;
    #pragma unroll
    for (int it = 0; it < 4; it++)
        if (sph[it] >= 0) in_s[0][sph[it]] = stv[it];
    __syncthreads();

    unsigned long long acc[4][8];
    #pragma unroll
    for (int op = 0; op < 4; op++)
        #pragma unroll
        for (int xx = 0; xx < 8; xx++) acc[op][xx] = 0ULL;

    for (int c = 0; c < 32; c++) {
        // prefetch next channel (LDG only; STS deferred to after compute)
        if (c + 1 < 32) {
            const float* nin = in + (size_t)(c + 1) * 16384;
            #pragma unroll
            for (int it = 0; it < 4; it++)
                stv[it] = (goff[it] >= 0) ? __ldg(nin + goff[it]) : 0.f;
        }

        const float* wc = w_s + c * 288;
        const float* ib = in_s[c & 1];
        #pragma unroll
        for (int i = 0; i < 3; i++) {
            unsigned long long xd[10];
            #pragma unroll
            for (int t2 = 0; t2 < 10; t2++)
                xd[t2] = pk2(ib[sidx(r + i, p * 8 + t2)]);
            #pragma unroll
            for (int j = 0; j < 3; j++) {
                unsigned long long w2r[4];
                #pragma unroll
                for (int op = 0; op < 4; op++)
                    w2r[op] = *(const unsigned long long*)(wc + i * 96 + j * 32 + og * 8 + 2 * op);
                #pragma unroll
                for (int xx = 0; xx < 8; xx++)
                    #pragma unroll
                    for (int op = 0; op < 4; op++)
                        fma2(acc[op][xx], w2r[op], xd[xx + j]);
            }
        }

        if (c + 1 < 32) {
            int nb = (c + 1) & 1;
            #pragma unroll
            for (int it = 0; it < 4; it++)
                if (sph[it] >= 0) in_s[nb][sph[it]] = stv[it];
        }
        __syncthreads();
    }

    // ---- epilogue: add mixed bias, store (two channels per op-pair) ----
    const float* bm = g_bmix + (ten * 16 + b) * 32;
    int y = y0 + r;
    #pragma unroll
    for (int op = 0; op < 4; op++) {
        int o0 = og * 8 + 2 * op;
        float bl = bm[o0], bh = bm[o0 + 1];
        float vl[8], vh[8];
        #pragma unroll
        for (int xx = 0; xx < 8; xx++) unpk(acc[op][xx], vl[xx], vh[xx]);
        size_t ob = ((size_t)(ten * 16 + b) * 32 + o0) * 16384 + (size_t)y * 128 + p * 8;
        float4 q;
        q.x = vl[0] + bl; q.y = vl[1] + bl; q.z = vl[2] + bl; q.w = vl[3] + bl;
        *(float4*)(out + ob) = q;
        q.x = vl[4] + bl; q.y = vl[5] + bl; q.z = vl[6] + bl; q.w = vl[7] + bl;
        *(float4*)(out + ob + 4) = q;
        q.x = vh[0] + bh; q.y = vh[1] + bh; q.z = vh[2] + bh; q.w = vh[3] + bh;
        *(float4*)(out + ob + 16384) = q;
        q.x = vh[4] + bh; q.y = vh[5] + bh; q.z = vh[6] + bh; q.w = vh[7] + bh;
        *(float4*)(out + ob + 16384 + 4) = q;
    }
}

// ================= launch =================
extern "C" void kernel_launch(void* const* d_in, const int* in_sizes, int n_in,
                              void* d_out, int out_size) {
    const float* center    = (const float*)d_in[0];
    const float* boundary  = (const float*)d_in[1];
    const float* aw        = (const float*)d_in[2];
    const float* ab        = (const float*)d_in[3];

    pool_kernel<<<1024, 256>>>(center, boundary);
    gate_mix_kernel<<<32, 256>>>(
        aw, ab,
        (const float*)d_in[4],  (const float*)d_in[5],  (const float*)d_in[6],
        (const float*)d_in[7],  (const float*)d_in[8],
        (const float*)d_in[9],  (const float*)d_in[10], (const float*)d_in[11],
        (const float*)d_in[12], (const float*)d_in[13], (const float*)d_in[14],
        (const float*)d_in[15], (const float*)d_in[16], (const float*)d_in[17],
        (const float*)d_in[18], (const float*)d_in[19],
        (const float*)d_in[20], (const float*)d_in[21], (const float*)d_in[22],
        (const float*)d_in[23], (const float*)d_in[24], (const float*)d_in[25]);
    conv_kernel<<<1024, 256>>>(center, boundary, (float*)d_out);
}

// round 4
// speedup vs baseline: 1.1086x; 1.0079x over previous
#include <cuda_runtime.h>
#include <math.h>

// Problem constants: B=16, C=32, O=32, K=3, H=W=128, T=34, EPS=1e-5
#define EPSF 1e-5f

// ---------------- scratch (no allocations allowed) ----------------
__device__ float g_pooled[16 * 64];              // [B][2C]
__device__ float g_wmix[2 * 16 * 32 * 9 * 32];   // [branch][B][c][tap][o]  (1.18 MB)
__device__ float g_bmix[2 * 16 * 32];            // [branch][B][o]

// ================= pool: mean over HxW of concat(center,boundary) =================
// 4 independent float4 loads in flight per iteration (MLP=4) to lift DRAM%.
__global__ void pool_kernel(const float* __restrict__ center,
                            const float* __restrict__ boundary) {
    int bid = blockIdx.x;            // 16*64 blocks
    int b = bid >> 6, ch = bid & 63;
    const float* src = (ch < 32)
        ? center   + (size_t)(b * 32 + ch)      * 16384
        : boundary + (size_t)(b * 32 + ch - 32) * 16384;
    const float4* s4 = (const float4*)src;
    int t = threadIdx.x;
    float s0 = 0.f, s1 = 0.f, s2 = 0.f, s3 = 0.f;
    #pragma unroll
    for (int i = 0; i < 4; i++) {
        float4 a = s4[t + i * 1024];
        float4 bq = s4[t + i * 1024 + 256];
        float4 cq = s4[t + i * 1024 + 512];
        float4 dq = s4[t + i * 1024 + 768];
        s0 += (a.x + a.y) + (a.z + a.w);
        s1 += (bq.x + bq.y) + (bq.z + bq.w);
        s2 += (cq.x + cq.y) + (cq.z + cq.w);
        s3 += (dq.x + dq.y) + (dq.z + dq.w);
    }
    float s = (s0 + s1) + (s2 + s3);
    #pragma unroll
    for (int off = 16; off; off >>= 1) s += __shfl_down_sync(0xffffffffu, s, off);
    __shared__ float red[8];
    if ((t & 31) == 0) red[t >> 5] = s;
    __syncthreads();
    if (t == 0) {
        float tt = 0.f;
        #pragma unroll
        for (int w = 0; w < 8; w++) tt += red[w];
        g_pooled[b * 64 + ch] = tt * (1.0f / 16384.0f);
    }
}

// ===== profiler-alignment probe: no-op so conv lands at captured launch idx 3 =====
__global__ void probe_kernel() {}

// ======== gate+mix: fc->BN->relu->fc->BN->softmax, then weight mixing ========
__global__ __launch_bounds__(256, 1)
void gate_mix_kernel(
    const float* __restrict__ aw,   const float* __restrict__ ab,
    const float* __restrict__ w1a,  const float* __restrict__ g1a,
    const float* __restrict__ b1a,  const float* __restrict__ rm1a,
    const float* __restrict__ rv1a,
    const float* __restrict__ w2a,  const float* __restrict__ bias2a,
    const float* __restrict__ g2a,  const float* __restrict__ b2a,
    const float* __restrict__ rm2a, const float* __restrict__ rv2a,
    const float* __restrict__ w1b,  const float* __restrict__ g1b,
    const float* __restrict__ b1b,  const float* __restrict__ rm1b,
    const float* __restrict__ rv1b,
    const float* __restrict__ w2b,  const float* __restrict__ bias2b,
    const float* __restrict__ g2b,  const float* __restrict__ b2b,
    const float* __restrict__ rm2b, const float* __restrict__ rv2b) {

    int bid = blockIdx.x;
    int ten = bid >> 4, b = bid & 15;
    int t = threadIdx.x;

    const float* w1    = ten ? w1b    : w1a;
    const float* g1    = ten ? g1b    : g1a;
    const float* bb1   = ten ? b1b    : b1a;
    const float* rm1   = ten ? rm1b   : rm1a;
    const float* rv1   = ten ? rv1b   : rv1a;
    const float* w2    = ten ? w2b    : w2a;
    const float* bias2 = ten ? bias2b : bias2a;
    const float* g2    = ten ? g2b    : g2a;
    const float* bb2   = ten ? b2b    : b2a;
    const float* rm2   = ten ? rm2b   : rm2a;
    const float* rv2   = ten ? rv2b   : rv2a;

    __shared__ float xs[64], hs[64], th[96], mred[2], thm[3];
    __shared__ float buf[9248];   // 9216 + per-o-row pad of 1

    // ---- gate branch ----
    if (t < 64) xs[t] = g_pooled[b * 64 + t];
    __syncthreads();
    if (t < 64) {
        float s = 0.f;
        #pragma unroll 8
        for (int i = 0; i < 64; i++) s += xs[i] * w1[t * 64 + i];
        s = (s - rm1[t]) * rsqrtf(rv1[t] + EPSF) * g1[t] + bb1[t];
        hs[t] = fmaxf(s, 0.f);
    }
    __syncthreads();
    if (t < 96) {
        float s = bias2[t];
        #pragma unroll 8
        for (int i = 0; i < 64; i++) s += hs[i] * w2[t * 64 + i];
        s = (s - rm2[t]) * rsqrtf(rv2[t] + EPSF) * g2[t] + bb2[t];
        th[t] = s * (1.0f / 34.0f);     // z/T
    }
    __syncthreads();
    if (t == 0) {
        float m = -1e30f;
        for (int i = 0; i < 96; i++) m = fmaxf(m, th[i]);
        mred[0] = m;
    }
    __syncthreads();
    if (t < 96) th[t] = expf(th[t] - mred[0]);
    __syncthreads();
    if (t == 0) {
        float s = 0.f;
        for (int i = 0; i < 96; i++) s += th[i];
        mred[1] = 1.0f / s;
    }
    __syncthreads();
    if (t < 96) th[t] *= mred[1];       // softmax done -> theta in th[]
    __syncthreads();

    // ---- bmix ----
    if (t < 3) {
        float s = 0.f;
        for (int c = 0; c < 32; c++) s += th[t * 32 + c];
        thm[t] = s * (1.0f / 32.0f);
    }
    __syncthreads();
    if (t < 32) {
        float s = 0.f;
        #pragma unroll
        for (int k = 0; k < 3; k++) s += thm[k] * ab[k * 32 + t];
        g_bmix[(ten * 16 + b) * 32 + t] = s;
    }

    // ---- wmix: wacc[d] = sum_k th[32k+c] * aw[k][o][c][ij], d = 288c+32ij+o ----
    float wacc[36];
    #pragma unroll
    for (int i = 0; i < 36; i++) wacc[i] = 0.f;

    int gidx[36]; float thc[3][36];
    #pragma unroll
    for (int i = 0; i < 36; i++) {
        int d  = t + i * 256;
        int c  = d / 288;
        int rr = d - c * 288;
        int ij = rr >> 5;
        int o  = rr & 31;
        gidx[i] = 289 * o + 9 * c + ij;
        thc[0][i] = th[c]; thc[1][i] = th[32 + c]; thc[2][i] = th[64 + c];
    }

    #pragma unroll
    for (int k = 0; k < 3; k++) {
        const float* awk = aw + k * 9216;
        #pragma unroll
        for (int i = 0; i < 36; i++) {
            int e = t + i * 256;
            buf[e + e / 288] = __ldg(awk + e);
        }
        __syncthreads();
        #pragma unroll
        for (int i = 0; i < 36; i++)
            wacc[i] += thc[k][i] * buf[gidx[i]];
        __syncthreads();
    }

    float* wm = g_wmix + (size_t)(ten * 16 + b) * 9216;
    #pragma unroll
    for (int i = 0; i < 36; i++) wm[t + i * 256] = wacc[i];
}

// ================= conv: per-sample 32->32ch 3x3, f32x2-packed FMA =================
#define RS 148   // skewed smem row stride (== 4 mod 32): stride-8 reads conflict-free

__device__ __forceinline__ int sidx(int row, int xw) {
    return row * RS + xw + (xw >> 5);
}
__device__ __forceinline__ unsigned long long pk2(float v) {
    unsigned long long r;
    asm("mov.b64 %0, {%1, %1};" : "=l"(r) : "f"(v));
    return r;
}
__device__ __forceinline__ void fma2(unsigned long long& d,
                                     unsigned long long a, unsigned long long b) {
    asm("fma.rn.f32x2 %0, %1, %2, %0;" : "+l"(d) : "l"(a), "l"(b));
}
__device__ __forceinline__ void unpk(unsigned long long v, float& lo, float& hi) {
    asm("mov.b64 {%0, %1}, %2;" : "=f"(lo), "=f"(hi) : "l"(v));
}

__global__ __launch_bounds__(256, 2)
void conv_kernel(const float* __restrict__ center,
                 const float* __restrict__ boundary,
                 float* __restrict__ out) {
    __shared__ float w_s[9216];          // [c][tap][o]  36 KB
    __shared__ float in_s[2][6 * RS];    // 2 x (6 rows, skewed) ~7 KB

    int bid = blockIdx.x;                // 2*16*32 = 1024 blocks
    int ten = bid >> 9;
    int b   = (bid >> 5) & 15;
    int y0  = (bid & 31) * 4;

    int tid = threadIdx.x;
    int og  = tid >> 6;        // 4 groups of 8 output channels
    int r   = (tid >> 4) & 3;  // row within 4-row tile
    int p   = tid & 15;        // x block (8 px each)

    const float* in = (ten == 0 ? center : boundary) + (size_t)b * 32 * 16384;

    // ---- load mixed weights into smem (float4, coalesced) ----
    {
        const float4* src = (const float4*)(g_wmix + (size_t)(ten * 16 + b) * 9216);
        float4* dst = (float4*)w_s;
        #pragma unroll
        for (int e = 0; e < 9; e++) dst[tid + e * 256] = src[tid + e * 256];
    }

    // ---- precompute staging addresses (identical across channels) ----
    int goff[4], sph[4];
    #pragma unroll
    for (int it = 0; it < 4; it++) {
        int u = tid + it * 256;      // 6 rows x 131 xw entries = 786
        goff[it] = -1; sph[it] = -1;
        if (u < 786) {
            int row = u / 131, xw = u - row * 131;
            int y = y0 - 1 + row, x = xw - 1;
            sph[it] = sidx(row, xw);
            if ((unsigned)y < 128u && (unsigned)x < 128u) goff[it] = y * 128 + x;
        }
    }

    float stv[4];
    // stage channel 0
    #pragma unroll
    for (int it = 0; it < 4; it++)
        stv[it] = (goff[it] >= 0) ? __ldg(in + goff[it]) : 0.f;
    #pragma unroll
    for (int it = 0; it < 4; it++)
        if (sph[it] >= 0) in_s[0][sph[it]] = stv[it];
    __syncthreads();

    unsigned long long acc[4][8];
    #pragma unroll
    for (int op = 0; op < 4; op++)
        #pragma unroll
        for (int xx = 0; xx < 8; xx++) acc[op][xx] = 0ULL;

    for (int c = 0; c < 32; c++) {
        // prefetch next channel (LDG only; STS deferred to after compute)
        if (c + 1 < 32) {
            const float* nin = in + (size_t)(c + 1) * 16384;
            #pragma unroll
            for (int it = 0; it < 4; it++)
                stv[it] = (goff[it] >= 0) ? __ldg(nin + goff[it]) : 0.f;
        }

        const float* wc = w_s + c * 288;
        const float* ib = in_s[c & 1];
        #pragma unroll
        for (int i = 0; i < 3; i++) {
            unsigned long long xd[10];
            #pragma unroll
            for (int t2 = 0; t2 < 10; t2++)
                xd[t2] = pk2(ib[sidx(r + i, p * 8 + t2)]);
            #pragma unroll
            for (int j = 0; j < 3; j++) {
                unsigned long long w2r[4];
                #pragma unroll
                for (int op = 0; op < 4; op++)
                    w2r[op] = *(const unsigned long long*)(wc + i * 96 + j * 32 + og * 8 + 2 * op);
                #pragma unroll
                for (int xx = 0; xx < 8; xx++)
                    #pragma unroll
                    for (int op = 0; op < 4; op++)
                        fma2(acc[op][xx], w2r[op], xd[xx + j]);
            }
        }

        if (c + 1 < 32) {
            int nb = (c + 1) & 1;
            #pragma unroll
            for (int it = 0; it < 4; it++)
                if (sph[it] >= 0) in_s[nb][sph[it]] = stv[it];
        }
        __syncthreads();
    }

    // ---- epilogue: add mixed bias, store (two channels per op-pair) ----
    const float* bm = g_bmix + (ten * 16 + b) * 32;
    int y = y0 + r;
    #pragma unroll
    for (int op = 0; op < 4; op++) {
        int o0 = og * 8 + 2 * op;
        float bl = bm[o0], bh = bm[o0 + 1];
        float vl[8], vh[8];
        #pragma unroll
        for (int xx = 0; xx < 8; xx++) unpk(acc[op][xx], vl[xx], vh[xx]);
        size_t ob = ((size_t)(ten * 16 + b) * 32 + o0) * 16384 + (size_t)y * 128 + p * 8;
        float4 q;
        q.x = vl[0] + bl; q.y = vl[1] + bl; q.z = vl[2] + bl; q.w = vl[3] + bl;
        *(float4*)(out + ob) = q;
        q.x = vl[4] + bl; q.y = vl[5] + bl; q.z = vl[6] + bl; q.w = vl[7] + bl;
        *(float4*)(out + ob + 4) = q;
        q.x = vh[0] + bh; q.y = vh[1] + bh; q.z = vh[2] + bh; q.w = vh[3] + bh;
        *(float4*)(out + ob + 16384) = q;
        q.x = vh[4] + bh; q.y = vh[5] + bh; q.z = vh[6] + bh; q.w = vh[7] + bh;
        *(float4*)(out + ob + 16384 + 4) = q;
    }
}

// ================= launch =================
extern "C" void kernel_launch(void* const* d_in, const int* in_sizes, int n_in,
                              void* d_out, int out_size) {
    const float* center    = (const float*)d_in[0];
    const float* boundary  = (const float*)d_in[1];
    const float* aw        = (const float*)d_in[2];
    const float* ab        = (const float*)d_in[3];

    pool_kernel<<<1024, 256>>>(center, boundary);
    gate_mix_kernel<<<32, 256>>>(
        aw, ab,
        (const float*)d_in[4],  (const float*)d_in[5],  (const float*)d_in[6],
        (const float*)d_in[7],  (const float*)d_in[8],
        (const float*)d_in[9],  (const float*)d_in[10], (const float*)d_in[11],
        (const float*)d_in[12], (const float*)d_in[13], (const float*)d_in[14],
        (const float*)d_in[15], (const float*)d_in[16], (const float*)d_in[17],
        (const float*)d_in[18], (const float*)d_in[19],
        (const float*)d_in[20], (const float*)d_in[21], (const float*)d_in[22],
        (const float*)d_in[23], (const float*)d_in[24], (const float*)d_in[25]);
    probe_kernel<<<1, 32>>>();   // alignment: conv becomes captured launch idx 3
    conv_kernel<<<1024, 256>>>(center, boundary, (float*)d_out);
}

// round 5
// speedup vs baseline: 1.1138x; 1.0047x over previous
#include <cuda_runtime.h>
#include <math.h>

// Problem constants: B=16, C=32, O=32, K=3, H=W=128, T=34, EPS=1e-5
#define EPSF 1e-5f

// ---------------- scratch (no allocations allowed) ----------------
__device__ float g_pooled[16 * 64];              // [B][2C]
__device__ float g_wmix[2 * 16 * 32 * 9 * 32];   // [branch][B][c][tap][o]  (1.18 MB)
__device__ float g_bmix[2 * 16 * 32];            // [branch][B][o]

// ================= pool: mean over HxW of concat(center,boundary) =================
// 4 independent float4 loads in flight per iteration (MLP=4) to lift DRAM%.
__global__ void pool_kernel(const float* __restrict__ center,
                            const float* __restrict__ boundary) {
    int bid = blockIdx.x;            // 16*64 blocks
    int b = bid >> 6, ch = bid & 63;
    const float* src = (ch < 32)
        ? center   + (size_t)(b * 32 + ch)      * 16384
        : boundary + (size_t)(b * 32 + ch - 32) * 16384;
    const float4* s4 = (const float4*)src;
    int t = threadIdx.x;
    float s0 = 0.f, s1 = 0.f, s2 = 0.f, s3 = 0.f;
    #pragma unroll
    for (int i = 0; i < 4; i++) {
        float4 a = s4[t + i * 1024];
        float4 bq = s4[t + i * 1024 + 256];
        float4 cq = s4[t + i * 1024 + 512];
        float4 dq = s4[t + i * 1024 + 768];
        s0 += (a.x + a.y) + (a.z + a.w);
        s1 += (bq.x + bq.y) + (bq.z + bq.w);
        s2 += (cq.x + cq.y) + (cq.z + cq.w);
        s3 += (dq.x + dq.y) + (dq.z + dq.w);
    }
    float s = (s0 + s1) + (s2 + s3);
    #pragma unroll
    for (int off = 16; off; off >>= 1) s += __shfl_down_sync(0xffffffffu, s, off);
    __shared__ float red[8];
    if ((t & 31) == 0) red[t >> 5] = s;
    __syncthreads();
    if (t == 0) {
        float tt = 0.f;
        #pragma unroll
        for (int w = 0; w < 8; w++) tt += red[w];
        g_pooled[b * 64 + ch] = tt * (1.0f / 16384.0f);
    }
}

// ===== profiler-alignment probe: no-op so conv lands at captured launch idx 3 =====
__global__ void probe_kernel() {}

// ======== gate+mix: fc->BN->relu->fc->BN->softmax, then weight mixing ========
__global__ __launch_bounds__(256, 1)
void gate_mix_kernel(
    const float* __restrict__ aw,   const float* __restrict__ ab,
    const float* __restrict__ w1a,  const float* __restrict__ g1a,
    const float* __restrict__ b1a,  const float* __restrict__ rm1a,
    const float* __restrict__ rv1a,
    const float* __restrict__ w2a,  const float* __restrict__ bias2a,
    const float* __restrict__ g2a,  const float* __restrict__ b2a,
    const float* __restrict__ rm2a, const float* __restrict__ rv2a,
    const float* __restrict__ w1b,  const float* __restrict__ g1b,
    const float* __restrict__ b1b,  const float* __restrict__ rm1b,
    const float* __restrict__ rv1b,
    const float* __restrict__ w2b,  const float* __restrict__ bias2b,
    const float* __restrict__ g2b,  const float* __restrict__ b2b,
    const float* __restrict__ rm2b, const float* __restrict__ rv2b) {

    int bid = blockIdx.x;
    int ten = bid >> 4, b = bid & 15;
    int t = threadIdx.x;

    const float* w1    = ten ? w1b    : w1a;
    const float* g1    = ten ? g1b    : g1a;
    const float* bb1   = ten ? b1b    : b1a;
    const float* rm1   = ten ? rm1b   : rm1a;
    const float* rv1   = ten ? rv1b   : rv1a;
    const float* w2    = ten ? w2b    : w2a;
    const float* bias2 = ten ? bias2b : bias2a;
    const float* g2    = ten ? g2b    : g2a;
    const float* bb2   = ten ? b2b    : b2a;
    const float* rm2   = ten ? rm2b   : rm2a;
    const float* rv2   = ten ? rv2b   : rv2a;

    __shared__ float xs[64], hs[64], th[96], mred[2], thm[3];
    __shared__ float buf[9248];   // 9216 + per-o-row pad of 1

    // ---- gate branch ----
    if (t < 64) xs[t] = g_pooled[b * 64 + t];
    __syncthreads();
    if (t < 64) {
        float s = 0.f;
        #pragma unroll 8
        for (int i = 0; i < 64; i++) s += xs[i] * w1[t * 64 + i];
        s = (s - rm1[t]) * rsqrtf(rv1[t] + EPSF) * g1[t] + bb1[t];
        hs[t] = fmaxf(s, 0.f);
    }
    __syncthreads();
    if (t < 96) {
        float s = bias2[t];
        #pragma unroll 8
        for (int i = 0; i < 64; i++) s += hs[i] * w2[t * 64 + i];
        s = (s - rm2[t]) * rsqrtf(rv2[t] + EPSF) * g2[t] + bb2[t];
        th[t] = s * (1.0f / 34.0f);     // z/T
    }
    __syncthreads();
    if (t == 0) {
        float m = -1e30f;
        for (int i = 0; i < 96; i++) m = fmaxf(m, th[i]);
        mred[0] = m;
    }
    __syncthreads();
    if (t < 96) th[t] = expf(th[t] - mred[0]);
    __syncthreads();
    if (t == 0) {
        float s = 0.f;
        for (int i = 0; i < 96; i++) s += th[i];
        mred[1] = 1.0f / s;
    }
    __syncthreads();
    if (t < 96) th[t] *= mred[1];       // softmax done -> theta in th[]
    __syncthreads();

    // ---- bmix ----
    if (t < 3) {
        float s = 0.f;
        for (int c = 0; c < 32; c++) s += th[t * 32 + c];
        thm[t] = s * (1.0f / 32.0f);
    }
    __syncthreads();
    if (t < 32) {
        float s = 0.f;
        #pragma unroll
        for (int k = 0; k < 3; k++) s += thm[k] * ab[k * 32 + t];
        g_bmix[(ten * 16 + b) * 32 + t] = s;
    }

    // ---- wmix: wacc[d] = sum_k th[32k+c] * aw[k][o][c][ij], d = 288c+32ij+o ----
    float wacc[36];
    #pragma unroll
    for (int i = 0; i < 36; i++) wacc[i] = 0.f;

    int gidx[36]; float thc[3][36];
    #pragma unroll
    for (int i = 0; i < 36; i++) {
        int d  = t + i * 256;
        int c  = d / 288;
        int rr = d - c * 288;
        int ij = rr >> 5;
        int o  = rr & 31;
        gidx[i] = 289 * o + 9 * c + ij;
        thc[0][i] = th[c]; thc[1][i] = th[32 + c]; thc[2][i] = th[64 + c];
    }

    #pragma unroll
    for (int k = 0; k < 3; k++) {
        const float* awk = aw + k * 9216;
        #pragma unroll
        for (int i = 0; i < 36; i++) {
            int e = t + i * 256;
            buf[e + e / 288] = __ldg(awk + e);
        }
        __syncthreads();
        #pragma unroll
        for (int i = 0; i < 36; i++)
            wacc[i] += thc[k][i] * buf[gidx[i]];
        __syncthreads();
    }

    float* wm = g_wmix + (size_t)(ten * 16 + b) * 9216;
    #pragma unroll
    for (int i = 0; i < 36; i++) wm[t + i * 256] = wacc[i];
}

// ================= conv: per-sample 32->32ch 3x3, f32x2-packed FMA =================
#define RS 148   // skewed smem row stride (== 4 mod 32): stride-8 reads conflict-free

__device__ __forceinline__ int sidx(int row, int xw) {
    return row * RS + xw + (xw >> 5);
}
__device__ __forceinline__ unsigned long long pk2(float v) {
    unsigned long long r;
    asm("mov.b64 %0, {%1, %1};" : "=l"(r) : "f"(v));
    return r;
}
__device__ __forceinline__ void fma2(unsigned long long& d,
                                     unsigned long long a, unsigned long long b) {
    asm("fma.rn.f32x2 %0, %1, %2, %0;" : "+l"(d) : "l"(a), "l"(b));
}
__device__ __forceinline__ void unpk(unsigned long long v, float& lo, float& hi) {
    asm("mov.b64 {%0, %1}, %2;" : "=f"(lo), "=f"(hi) : "l"(v));
}

__global__ __launch_bounds__(256, 2)
void conv_kernel(const float* __restrict__ center,
                 const float* __restrict__ boundary,
                 float* __restrict__ out) {
    __shared__ float w_s[9216];          // [c][tap][o]  36 KB
    __shared__ float in_s[2][6 * RS];    // 2 x (6 rows, skewed) ~7 KB

    int bid = blockIdx.x;                // 2*16*32 = 1024 blocks
    int ten = bid >> 9;
    int b   = (bid >> 5) & 15;
    int y0  = (bid & 31) * 4;

    int tid = threadIdx.x;
    int og  = tid >> 6;        // 4 groups of 8 output channels
    int r   = (tid >> 4) & 3;  // row within 4-row tile
    int p   = tid & 15;        // x block (8 px each)

    const float* in = (ten == 0 ? center : boundary) + (size_t)b * 32 * 16384;

    // ---- load mixed weights into smem (float4, coalesced) ----
    {
        const float4* src = (const float4*)(g_wmix + (size_t)(ten * 16 + b) * 9216);
        float4* dst = (float4*)w_s;
        #pragma unroll
        for (int e = 0; e < 9; e++) dst[tid + e * 256] = src[tid + e * 256];
    }

    // ---- precompute staging addresses (identical across channels) ----
    int goff[4], sph[4];
    #pragma unroll
    for (int it = 0; it < 4; it++) {
        int u = tid + it * 256;      // 6 rows x 131 xw entries = 786
        goff[it] = -1; sph[it] = -1;
        if (u < 786) {
            int row = u / 131, xw = u - row * 131;
            int y = y0 - 1 + row, x = xw - 1;
            sph[it] = sidx(row, xw);
            if ((unsigned)y < 128u && (unsigned)x < 128u) goff[it] = y * 128 + x;
        }
    }

    float stv[4];
    // stage channel 0
    #pragma unroll
    for (int it = 0; it < 4; it++)
        stv[it] = (goff[it] >= 0) ? __ldg(in + goff[it]) : 0.f;
    #pragma unroll
    for (int it = 0; it < 4; it++)
        if (sph[it] >= 0) in_s[0][sph[it]] = stv[it];
    __syncthreads();

    unsigned long long acc[4][8];
    #pragma unroll
    for (int op = 0; op < 4; op++)
        #pragma unroll
        for (int xx = 0; xx < 8; xx++) acc[op][xx] = 0ULL;

    for (int c = 0; c < 32; c++) {
        // prefetch next channel (LDG only; STS deferred to after compute)
        if (c + 1 < 32) {
            const float* nin = in + (size_t)(c + 1) * 16384;
            #pragma unroll
            for (int it = 0; it < 4; it++)
                stv[it] = (goff[it] >= 0) ? __ldg(nin + goff[it]) : 0.f;
        }

        const float* wc = w_s + c * 288;
        const float* ib = in_s[c & 1];
        #pragma unroll
        for (int i = 0; i < 3; i++) {
            unsigned long long xd[10];
            #pragma unroll
            for (int t2 = 0; t2 < 10; t2++)
                xd[t2] = pk2(ib[sidx(r + i, p * 8 + t2)]);
            #pragma unroll
            for (int j = 0; j < 3; j++) {
                unsigned long long w2r[4];
                #pragma unroll
                for (int op = 0; op < 4; op++)
                    w2r[op] = *(const unsigned long long*)(wc + i * 96 + j * 32 + og * 8 + 2 * op);
                #pragma unroll
                for (int xx = 0; xx < 8; xx++)
                    #pragma unroll
                    for (int op = 0; op < 4; op++)
                        fma2(acc[op][xx], w2r[op], xd[xx + j]);
            }
        }

        if (c + 1 < 32) {
            int nb = (c + 1) & 1;
            #pragma unroll
            for (int it = 0; it < 4; it++)
                if (sph[it] >= 0) in_s[nb][sph[it]] = stv[it];
        }
        __syncthreads();
    }

    // ---- epilogue: add mixed bias, store (two channels per op-pair) ----
    const float* bm = g_bmix + (ten * 16 + b) * 32;
    int y = y0 + r;
    #pragma unroll
    for (int op = 0; op < 4; op++) {
        int o0 = og * 8 + 2 * op;
        float bl = bm[o0], bh = bm[o0 + 1];
        float vl[8], vh[8];
        #pragma unroll
        for (int xx = 0; xx < 8; xx++) unpk(acc[op][xx], vl[xx], vh[xx]);
        size_t ob = ((size_t)(ten * 16 + b) * 32 + o0) * 16384 + (size_t)y * 128 + p * 8;
        float4 q;
        q.x = vl[0] + bl; q.y = vl[1] + bl; q.z = vl[2] + bl; q.w = vl[3] + bl;
        *(float4*)(out + ob) = q;
        q.x = vl[4] + bl; q.y = vl[5] + bl; q.z = vl[6] + bl; q.w = vl[7] + bl;
        *(float4*)(out + ob + 4) = q;
        q.x = vh[0] + bh; q.y = vh[1] + bh; q.z = vh[2] + bh; q.w = vh[3] + bh;
        *(float4*)(out + ob + 16384) = q;
        q.x = vh[4] + bh; q.y = vh[5] + bh; q.z = vh[6] + bh; q.w = vh[7] + bh;
        *(float4*)(out + ob + 16384 + 4) = q;
    }
}

// ================= launch =================
extern "C" void kernel_launch(void* const* d_in, const int* in_sizes, int n_in,
                              void* d_out, int out_size) {
    const float* center    = (const float*)d_in[0];
    const float* boundary  = (const float*)d_in[1];
    const float* aw        = (const float*)d_in[2];
    const float* ab        = (const float*)d_in[3];

    pool_kernel<<<1024, 256>>>(center, boundary);
    gate_mix_kernel<<<32, 256>>>(
        aw, ab,
        (const float*)d_in[4],  (const float*)d_in[5],  (const float*)d_in[6],
        (const float*)d_in[7],  (const float*)d_in[8],
        (const float*)d_in[9],  (const float*)d_in[10], (const float*)d_in[11],
        (const float*)d_in[12], (const float*)d_in[13], (const float*)d_in[14],
        (const float*)d_in[15], (const float*)d_in[16], (const float*)d_in[17],
        (const float*)d_in[18], (const float*)d_in[19],
        (const float*)d_in[20], (const float*)d_in[21], (const float*)d_in[22],
        (const float*)d_in[23], (const float*)d_in[24], (const float*)d_in[25]);
    probe_kernel<<<1, 32>>>();   // alignment: conv becomes captured launch idx 3
    conv_kernel<<<1024, 256>>>(center, boundary, (float*)d_out);
}